// round 9
// baseline (speedup 1.0000x reference)
#include <cuda_runtime.h>
#include <cuda_bf16.h>
#include <cstdint>

// ---------------------------------------------------------------------------
// PatchLoss: sim = ref_patches @ shape_patches^T (argmax over U), then
// L1(out_patches, color_patch[argmax]) clipped at 1000, summed to scalar.
//
// Shapes: N=2, C=128, ref/out 64x64 (Hp=Wp=62 -> M=3844),
//         shape/color 128x128 (126x126 -> U=15876), K = C*9 = 1152.
// ---------------------------------------------------------------------------

#define NBATCH 2
#define CCH    128
#define H1     64
#define W1     64
#define H2     128
#define W2     128
#define HP     62
#define WP     62
#define MVALID (HP * WP)      // 3844
#define MPAD   3904           // 61 * 64
#define HS     126
#define UVALID (HS * HS)      // 15876
#define UPAD   16000          // 125 * 128
#define KDIM   1152

// GEMM tiling
#define MT  64
#define NT  128
#define KC  32
#define KP  40                // padded k stride (bf16 elems) -> 80B rows, conflict-free
#define NKI (KDIM / KC)       // 36
#define NNT (UPAD / NT)       // 125

// Scratch (device globals: allocation-free scratch per harness rules)
__device__ __nv_bfloat16 g_A[(size_t)NBATCH * MPAD * KDIM];   // ref patches   (~18 MB)
__device__ __nv_bfloat16 g_B[(size_t)NBATCH * UPAD * KDIM];   // shape patches (~74 MB)
__device__ int           g_idx[NBATCH * MPAD];

// ---------------------------------------------------------------------------
// Pack kernel: gather 3x3 patches into [row][k] bf16 matrix, k = c*9 + a*3 + b.
// Thread = (n, c, row) with row innermost -> coalesced global reads.
// Rows in [rows_valid, rows_pad) are zero-filled.
// ---------------------------------------------------------------------------
__global__ void pack_patches(const float* __restrict__ src,
                             __nv_bfloat16* __restrict__ dst,
                             int Hsrc, int Wsrc, int Wout,
                             int rows_valid, int rows_pad) {
    size_t t = (size_t)blockIdx.x * blockDim.x + threadIdx.x;
    size_t total = (size_t)NBATCH * CCH * rows_pad;
    if (t >= total) return;
    int row = (int)(t % rows_pad);
    int c   = (int)((t / rows_pad) % CCH);
    int n   = (int)(t / ((size_t)rows_pad * CCH));

    __nv_bfloat16* d = dst + ((size_t)n * rows_pad + row) * KDIM + c * 9;
    if (row >= rows_valid) {
        #pragma unroll
        for (int k = 0; k < 9; ++k) d[k] = __float2bfloat16(0.0f);
        return;
    }
    int i = row / Wout, j = row % Wout;
    const float* s = src + (((size_t)n * CCH + c) * Hsrc + i) * Wsrc + j;
    #pragma unroll
    for (int a = 0; a < 3; ++a)
        #pragma unroll
        for (int b = 0; b < 3; ++b)
            d[a * 3 + b] = __float2bfloat16(s[a * Wsrc + b]);
}

// ---------------------------------------------------------------------------
// GEMM + argmax: per CTA, an M-strip of 64 rows against all U (125 N-tiles),
// running per-row (max, idx) kept in registers, reduced at the end.
// ---------------------------------------------------------------------------
__device__ __forceinline__ void cp_async16(void* smem_dst, const void* gmem_src) {
    uint32_t d = (uint32_t)__cvta_generic_to_shared(smem_dst);
    asm volatile("cp.async.cg.shared.global [%0], [%1], 16;\n" :: "r"(d), "l"(gmem_src));
}

__global__ __launch_bounds__(256, 1) void gemm_argmax_kernel() {
    __shared__ __nv_bfloat16 As[2][MT][KP];
    __shared__ __nv_bfloat16 Bs[2][NT][KP];
    __shared__ float s_val[4][MT];
    __shared__ int   s_idx[4][MT];

    const int n  = blockIdx.y;
    const int m0 = blockIdx.x * MT;
    const __nv_bfloat16* Ag = g_A + ((size_t)n * MPAD + m0) * KDIM;
    const __nv_bfloat16* Bg = g_B + (size_t)n * UPAD * KDIM;

    const int tid  = threadIdx.x;
    const int lane = tid & 31;
    const int wid  = tid >> 5;
    const int wm   = wid >> 2;   // 0..1
    const int wn   = wid & 3;    // 0..3

    // cp.async mapping: 16B chunks, row stride KP elems in smem
    const int a_row = tid >> 2;
    const int a_kc  = (tid & 3) * 8;

    // ldmatrix lane mapping
    const int lrow = lane & 15;
    const int lcol = (lane >> 4) << 3;

    float bestv[4];
    int   besti[4];
    #pragma unroll
    for (int r = 0; r < 4; ++r) { bestv[r] = -3.0e38f; besti[r] = 0; }

    for (int nt = 0; nt < NNT; ++nt) {
        const __nv_bfloat16* Bt = Bg + (size_t)(nt * NT) * KDIM;

        float acc[2][4][4];
        #pragma unroll
        for (int mi = 0; mi < 2; ++mi)
            #pragma unroll
            for (int ni = 0; ni < 4; ++ni)
                #pragma unroll
                for (int q = 0; q < 4; ++q) acc[mi][ni][q] = 0.0f;

        // prologue: load k-iter 0 into buffer 0
        cp_async16(&As[0][a_row][a_kc], Ag + (size_t)a_row * KDIM + a_kc);
        cp_async16(&Bs[0][a_row][a_kc], Bt + (size_t)a_row * KDIM + a_kc);
        cp_async16(&Bs[0][a_row + 64][a_kc], Bt + (size_t)(a_row + 64) * KDIM + a_kc);
        asm volatile("cp.async.commit_group;\n");

        for (int kt = 0; kt < NKI; ++kt) {
            const int cur = kt & 1;
            if (kt + 1 < NKI) {
                const int nxt = cur ^ 1;
                const int k0 = (kt + 1) * KC;
                cp_async16(&As[nxt][a_row][a_kc], Ag + (size_t)a_row * KDIM + k0 + a_kc);
                cp_async16(&Bs[nxt][a_row][a_kc], Bt + (size_t)a_row * KDIM + k0 + a_kc);
                cp_async16(&Bs[nxt][a_row + 64][a_kc], Bt + (size_t)(a_row + 64) * KDIM + k0 + a_kc);
                asm volatile("cp.async.commit_group;\n");
                asm volatile("cp.async.wait_group 1;\n");
            } else {
                asm volatile("cp.async.wait_group 0;\n");
            }
            __syncthreads();

            #pragma unroll
            for (int kk = 0; kk < 2; ++kk) {
                uint32_t af[2][4], bf[4][2];
                #pragma unroll
                for (int mi = 0; mi < 2; ++mi) {
                    uint32_t addr = (uint32_t)__cvta_generic_to_shared(
                        &As[cur][wm * 32 + mi * 16 + lrow][kk * 16 + lcol]);
                    asm volatile("ldmatrix.sync.aligned.m8n8.x4.shared.b16 {%0,%1,%2,%3}, [%4];"
                        : "=r"(af[mi][0]), "=r"(af[mi][1]), "=r"(af[mi][2]), "=r"(af[mi][3])
                        : "r"(addr));
                }
                #pragma unroll
                for (int nh = 0; nh < 2; ++nh) {
                    uint32_t r0, r1, r2, r3;
                    uint32_t addr = (uint32_t)__cvta_generic_to_shared(
                        &Bs[cur][wn * 32 + nh * 16 + lrow][kk * 16 + lcol]);
                    asm volatile("ldmatrix.sync.aligned.m8n8.x4.shared.b16 {%0,%1,%2,%3}, [%4];"
                        : "=r"(r0), "=r"(r1), "=r"(r2), "=r"(r3) : "r"(addr));
                    bf[nh * 2 + 0][0] = r0; bf[nh * 2 + 0][1] = r2;
                    bf[nh * 2 + 1][0] = r1; bf[nh * 2 + 1][1] = r3;
                }
                #pragma unroll
                for (int mi = 0; mi < 2; ++mi)
                    #pragma unroll
                    for (int ni = 0; ni < 4; ++ni)
                        asm volatile(
                            "mma.sync.aligned.m16n8k16.row.col.f32.bf16.bf16.f32 "
                            "{%0,%1,%2,%3}, {%4,%5,%6,%7}, {%8,%9}, {%0,%1,%2,%3};"
                            : "+f"(acc[mi][ni][0]), "+f"(acc[mi][ni][1]),
                              "+f"(acc[mi][ni][2]), "+f"(acc[mi][ni][3])
                            : "r"(af[mi][0]), "r"(af[mi][1]), "r"(af[mi][2]), "r"(af[mi][3]),
                              "r"(bf[ni][0]), "r"(bf[ni][1]));
            }
            __syncthreads();
        }

        // running argmax update (mask padded u)
        #pragma unroll
        for (int mi = 0; mi < 2; ++mi)
            #pragma unroll
            for (int rh = 0; rh < 2; ++rh) {
                const int r = mi * 2 + rh;
                #pragma unroll
                for (int ni = 0; ni < 4; ++ni)
                    #pragma unroll
                    for (int ch = 0; ch < 2; ++ch) {
                        int u = nt * NT + wn * 32 + ni * 8 + (lane & 3) * 2 + ch;
                        float v = acc[mi][ni][rh * 2 + ch];
                        if (u < UVALID && v > bestv[r]) { bestv[r] = v; besti[r] = u; }
                    }
            }
    }

    // reduce across the 4 lanes of each quad (cols within warp)
    #pragma unroll
    for (int r = 0; r < 4; ++r) {
        #pragma unroll
        for (int off = 1; off <= 2; off <<= 1) {
            float ov = __shfl_xor_sync(0xffffffffu, bestv[r], off);
            int   oi = __shfl_xor_sync(0xffffffffu, besti[r], off);
            if (ov > bestv[r] || (ov == bestv[r] && oi < besti[r])) {
                bestv[r] = ov; besti[r] = oi;
            }
        }
    }
    if ((lane & 3) == 0) {
        #pragma unroll
        for (int r = 0; r < 4; ++r) {
            int mi = r >> 1, rh = r & 1;
            int row = wm * 32 + mi * 16 + rh * 8 + (lane >> 2);
            s_val[wn][row] = bestv[r];
            s_idx[wn][row] = besti[r];
        }
    }
    __syncthreads();
    if (tid < MT) {
        float bv = s_val[0][tid];
        int   bi = s_idx[0][tid];
        #pragma unroll
        for (int w = 1; w < 4; ++w) {
            float ov = s_val[w][tid];
            int   oi = s_idx[w][tid];
            if (ov > bv || (ov == bv && oi < bi)) { bv = ov; bi = oi; }
        }
        if (m0 + tid < MVALID) g_idx[n * MPAD + m0 + tid] = bi;
    }
}

// ---------------------------------------------------------------------------
// L1 + clip + sum: block per (n, position), 128 threads = channels.
// ---------------------------------------------------------------------------
__global__ __launch_bounds__(128) void l1_kernel(const float* __restrict__ outf,
                                                 const float* __restrict__ colf,
                                                 float* __restrict__ d_out) {
    const int pos = blockIdx.x;   // 0..MVALID-1
    const int n   = blockIdx.y;
    const int c   = threadIdx.x;  // 0..127

    const int i = pos / WP, j = pos % WP;
    const int u = g_idx[n * MPAD + pos];
    const int ui = u / HS, uj = u % HS;

    const float* po = outf + (((size_t)n * CCH + c) * H1 + i) * W1 + j;
    const float* pc = colf + (((size_t)n * CCH + c) * H2 + ui) * W2 + uj;

    float s = 0.0f;
    #pragma unroll
    for (int a = 0; a < 3; ++a)
        #pragma unroll
        for (int b = 0; b < 3; ++b)
            s += fabsf(po[a * W1 + b] - pc[a * W2 + b]);

    #pragma unroll
    for (int off = 16; off; off >>= 1) s += __shfl_xor_sync(0xffffffffu, s, off);

    __shared__ float ws[4];
    if ((threadIdx.x & 31) == 0) ws[threadIdx.x >> 5] = s;
    __syncthreads();
    if (threadIdx.x == 0) {
        float t = ws[0] + ws[1] + ws[2] + ws[3];
        atomicAdd(d_out, fminf(t, 1000.0f));
    }
}

__global__ void zero_out_kernel(float* p) { if (threadIdx.x == 0) p[0] = 0.0f; }

// ---------------------------------------------------------------------------
extern "C" void kernel_launch(void* const* d_in, const int* in_sizes, int n_in,
                              void* d_out, int out_size) {
    const float* outf = (const float*)d_in[0];
    const float* reff = (const float*)d_in[1];
    const float* shpf = (const float*)d_in[2];
    const float* colf = (const float*)d_in[3];
    float* out = (float*)d_out;

    zero_out_kernel<<<1, 32>>>(out);

    // Pack A (ref patches) and B (shape patches)
    {
        size_t totalA = (size_t)NBATCH * CCH * MPAD;
        int blocksA = (int)((totalA + 255) / 256);
        // dst pointers: take address of device symbols inside a kernel is not
        // possible from host; use a tiny trampoline via a device-side pointer.
        // Instead: pack_patches receives dst as a raw pointer. We obtain the
        // symbol addresses once via kernels writing into a device pointer is
        // overkill — cudaGetSymbolAddress is a non-stream host API, safe to
        // call here (no allocation, no stream op, graph-capture friendly).
        static void* pA = nullptr;
        static void* pB = nullptr;
        if (!pA) { cudaGetSymbolAddress(&pA, g_A); cudaGetSymbolAddress(&pB, g_B); }
        pack_patches<<<blocksA, 256>>>(reff, (__nv_bfloat16*)pA,
                                       H1, W1, WP, MVALID, MPAD);
        size_t totalB = (size_t)NBATCH * CCH * UPAD;
        int blocksB = (int)((totalB + 255) / 256);
        pack_patches<<<blocksB, 256>>>(shpf, (__nv_bfloat16*)pB,
                                       H2, W2, HS, UVALID, UPAD);
    }

    // GEMM + argmax: grid (61 M-tiles, 2 batches)
    gemm_argmax_kernel<<<dim3(MPAD / MT, NBATCH), 256>>>();

    // L1 + clip + sum
    l1_kernel<<<dim3(MVALID, NBATCH), 128>>>(outf, colf, out);
}

// round 11
// speedup vs baseline: 1.4585x; 1.4585x over previous
#include <cuda_runtime.h>
#include <cuda_bf16.h>
#include <cstdint>

// ---------------------------------------------------------------------------
// PatchLoss: sim = ref_patches @ shape_patches^T, per-row argmax over U,
// L1(out_patches, color_patch[argmax]) clipped at 1000, summed to scalar.
// N=2, C=128 -> K=1152; M=3844 (pad 3968); U=15876 (pad 16000).
// mma.sync (HMMA) path: harness ptxas targets sm_103 (no 'a'), tcgen05 rejected.
// ---------------------------------------------------------------------------

#define NBATCH 2
#define CCH    128
#define H1     64
#define W1     64
#define H2     128
#define W2     128
#define HP     62
#define WP     62
#define MVALID 3844
#define MPAD   3968           // 31 * 128
#define HS     126
#define UVALID 15876
#define UPAD   16000          // 125 * 128
#define KDIM   1152

// GEMM tiling
#define MT   128
#define NT   128
#define KC   32
#define KP   40               // padded k stride (bf16) -> 80B rows, conflict-free
#define NKI  (KDIM / KC)      // 36
#define NSPLIT 5
#define NT_PER_CTA 25         // 125 / 5

__device__ __nv_bfloat16 g_A[(size_t)NBATCH * MPAD * KDIM];   // ~18.3 MB
__device__ __nv_bfloat16 g_B[(size_t)NBATCH * UPAD * KDIM];   // ~73.7 MB
__device__ float g_pval[NBATCH * NSPLIT * MPAD];
__device__ int   g_pidx[NBATCH * NSPLIT * MPAD];
__device__ int   g_idx[NBATCH * MPAD];

// ---------------------------------------------------------------------------
// Pack: gather 3x3 patches into [row][k] bf16, k = c*9 + a*3 + b.
// ---------------------------------------------------------------------------
__global__ void pack_patches(const float* __restrict__ src,
                             __nv_bfloat16* __restrict__ dst,
                             int Hsrc, int Wsrc, int Wout,
                             int rows_valid, int rows_pad) {
    size_t t = (size_t)blockIdx.x * blockDim.x + threadIdx.x;
    size_t total = (size_t)NBATCH * CCH * rows_pad;
    if (t >= total) return;
    int row = (int)(t % rows_pad);
    int c   = (int)((t / rows_pad) % CCH);
    int n   = (int)(t / ((size_t)rows_pad * CCH));

    __nv_bfloat16* d = dst + ((size_t)n * rows_pad + row) * KDIM + c * 9;
    if (row >= rows_valid) {
        #pragma unroll
        for (int k = 0; k < 9; ++k) d[k] = __float2bfloat16(0.0f);
        return;
    }
    int i = row / Wout, j = row % Wout;
    const float* s = src + (((size_t)n * CCH + c) * Hsrc + i) * Wsrc + j;
    #pragma unroll
    for (int a = 0; a < 3; ++a)
        #pragma unroll
        for (int b = 0; b < 3; ++b)
            d[a * 3 + b] = __float2bfloat16(s[a * Wsrc + b]);
}

// ---------------------------------------------------------------------------
__device__ __forceinline__ void cp_async16(void* smem_dst, const void* gmem_src) {
    uint32_t d = (uint32_t)__cvta_generic_to_shared(smem_dst);
    asm volatile("cp.async.cg.shared.global [%0], [%1], 16;\n" :: "r"(d), "l"(gmem_src));
}

// ---------------------------------------------------------------------------
// GEMM + argmax: CTA tile 128x128, double-buffered cp.async, 8 warps (2x4),
// each warp 64x32.  Per-CTA: 25 N-tiles of its U-split, running per-row
// (max,idx), partials to g_pval/g_pidx.
// ---------------------------------------------------------------------------
__global__ __launch_bounds__(256, 2) void gemm_argmax_kernel() {
    __shared__ __nv_bfloat16 As[2][MT][KP];
    __shared__ __nv_bfloat16 Bs[2][NT][KP];
    __shared__ float s_val[4][MT];
    __shared__ int   s_idx[4][MT];

    const int m0 = blockIdx.x * MT;
    const int sp = blockIdx.y;
    const int n  = blockIdx.z;
    const __nv_bfloat16* Ag = g_A + ((size_t)n * MPAD + m0) * KDIM;
    const __nv_bfloat16* Bg = g_B + (size_t)n * UPAD * KDIM;

    const int tid  = threadIdx.x;
    const int lane = tid & 31;
    const int wid  = tid >> 5;
    const int wm   = wid >> 2;   // 0..1 -> rows wm*64
    const int wn   = wid & 3;    // 0..3 -> cols wn*32

    // cp.async mapping: 16B chunks; rows tid>>2 and (tid>>2)+64, chunk tid&3
    const int a_row = tid >> 2;
    const int a_kc  = (tid & 3) * 8;

    // ldmatrix lane mapping
    const int lrow = lane & 15;
    const int lcol = (lane >> 4) << 3;

    float bestv[8];
    int   besti[8];
    #pragma unroll
    for (int r = 0; r < 8; ++r) { bestv[r] = -3.0e38f; besti[r] = 0; }

    for (int nt = 0; nt < NT_PER_CTA; ++nt) {
        const __nv_bfloat16* Bt = Bg + (size_t)(sp * NT_PER_CTA + nt) * NT * KDIM;

        float acc[4][4][4];
        #pragma unroll
        for (int mi = 0; mi < 4; ++mi)
            #pragma unroll
            for (int ni = 0; ni < 4; ++ni)
                #pragma unroll
                for (int q = 0; q < 4; ++q) acc[mi][ni][q] = 0.0f;

        // prologue: k-chunk 0 into buffer 0
        cp_async16(&As[0][a_row][a_kc], Ag + (size_t)a_row * KDIM + a_kc);
        cp_async16(&As[0][a_row + 64][a_kc], Ag + (size_t)(a_row + 64) * KDIM + a_kc);
        cp_async16(&Bs[0][a_row][a_kc], Bt + (size_t)a_row * KDIM + a_kc);
        cp_async16(&Bs[0][a_row + 64][a_kc], Bt + (size_t)(a_row + 64) * KDIM + a_kc);
        asm volatile("cp.async.commit_group;\n");

        for (int kt = 0; kt < NKI; ++kt) {
            const int cur = kt & 1;
            if (kt + 1 < NKI) {
                const int nxt = cur ^ 1;
                const int k0 = (kt + 1) * KC;
                cp_async16(&As[nxt][a_row][a_kc], Ag + (size_t)a_row * KDIM + k0 + a_kc);
                cp_async16(&As[nxt][a_row + 64][a_kc], Ag + (size_t)(a_row + 64) * KDIM + k0 + a_kc);
                cp_async16(&Bs[nxt][a_row][a_kc], Bt + (size_t)a_row * KDIM + k0 + a_kc);
                cp_async16(&Bs[nxt][a_row + 64][a_kc], Bt + (size_t)(a_row + 64) * KDIM + k0 + a_kc);
                asm volatile("cp.async.commit_group;\n");
                asm volatile("cp.async.wait_group 1;\n");
            } else {
                asm volatile("cp.async.wait_group 0;\n");
            }
            __syncthreads();

            #pragma unroll
            for (int kk = 0; kk < 2; ++kk) {
                uint32_t af[4][4], bf[4][2];
                #pragma unroll
                for (int mi = 0; mi < 4; ++mi) {
                    uint32_t addr = (uint32_t)__cvta_generic_to_shared(
                        &As[cur][wm * 64 + mi * 16 + lrow][kk * 16 + lcol]);
                    asm volatile("ldmatrix.sync.aligned.m8n8.x4.shared.b16 {%0,%1,%2,%3}, [%4];"
                        : "=r"(af[mi][0]), "=r"(af[mi][1]), "=r"(af[mi][2]), "=r"(af[mi][3])
                        : "r"(addr));
                }
                #pragma unroll
                for (int nh = 0; nh < 2; ++nh) {
                    uint32_t r0, r1, r2, r3;
                    uint32_t addr = (uint32_t)__cvta_generic_to_shared(
                        &Bs[cur][wn * 32 + nh * 16 + lrow][kk * 16 + lcol]);
                    asm volatile("ldmatrix.sync.aligned.m8n8.x4.shared.b16 {%0,%1,%2,%3}, [%4];"
                        : "=r"(r0), "=r"(r1), "=r"(r2), "=r"(r3) : "r"(addr));
                    bf[nh * 2 + 0][0] = r0; bf[nh * 2 + 0][1] = r2;
                    bf[nh * 2 + 1][0] = r1; bf[nh * 2 + 1][1] = r3;
                }
                #pragma unroll
                for (int mi = 0; mi < 4; ++mi)
                    #pragma unroll
                    for (int ni = 0; ni < 4; ++ni)
                        asm volatile(
                            "mma.sync.aligned.m16n8k16.row.col.f32.bf16.bf16.f32 "
                            "{%0,%1,%2,%3}, {%4,%5,%6,%7}, {%8,%9}, {%0,%1,%2,%3};"
                            : "+f"(acc[mi][ni][0]), "+f"(acc[mi][ni][1]),
                              "+f"(acc[mi][ni][2]), "+f"(acc[mi][ni][3])
                            : "r"(af[mi][0]), "r"(af[mi][1]), "r"(af[mi][2]), "r"(af[mi][3]),
                              "r"(bf[ni][0]), "r"(bf[ni][1]));
            }
            __syncthreads();
        }

        // running argmax update (mask padded u)
        const int ubase = (sp * NT_PER_CTA + nt) * NT + wn * 32 + (lane & 3) * 2;
        #pragma unroll
        for (int mi = 0; mi < 4; ++mi)
            #pragma unroll
            for (int rh = 0; rh < 2; ++rh) {
                const int r = mi * 2 + rh;
                #pragma unroll
                for (int ni = 0; ni < 4; ++ni)
                    #pragma unroll
                    for (int ch = 0; ch < 2; ++ch) {
                        int u = ubase + ni * 8 + ch;
                        float v = acc[mi][ni][rh * 2 + ch];
                        if (u < UVALID && v > bestv[r]) { bestv[r] = v; besti[r] = u; }
                    }
            }
    }

    // reduce across the 4 lanes of each quad (cols within warp)
    #pragma unroll
    for (int r = 0; r < 8; ++r) {
        #pragma unroll
        for (int off = 1; off <= 2; off <<= 1) {
            float ov = __shfl_xor_sync(0xffffffffu, bestv[r], off);
            int   oi = __shfl_xor_sync(0xffffffffu, besti[r], off);
            if (ov > bestv[r] || (ov == bestv[r] && oi < besti[r])) {
                bestv[r] = ov; besti[r] = oi;
            }
        }
    }
    if ((lane & 3) == 0) {
        #pragma unroll
        for (int r = 0; r < 8; ++r) {
            int mi = r >> 1, rh = r & 1;
            int row = wm * 64 + mi * 16 + rh * 8 + (lane >> 2);
            s_val[wn][row] = bestv[r];
            s_idx[wn][row] = besti[r];
        }
    }
    __syncthreads();
    if (tid < MT) {
        float bv = s_val[0][tid];
        int   bi = s_idx[0][tid];
        #pragma unroll
        for (int w = 1; w < 4; ++w) {
            float ov = s_val[w][tid];
            int   oi = s_idx[w][tid];
            if (ov > bv || (ov == bv && oi < bi)) { bv = ov; bi = oi; }
        }
        if (m0 + tid < MVALID) {
            const size_t o = ((size_t)n * NSPLIT + sp) * MPAD + m0 + tid;
            g_pval[o] = bv;
            g_pidx[o] = bi;
        }
    }
}

// ---------------------------------------------------------------------------
// Combine split partials (ascending split = ascending u -> first-max kept).
// ---------------------------------------------------------------------------
__global__ void reduce_argmax_kernel() {
    int t = blockIdx.x * blockDim.x + threadIdx.x;
    if (t >= NBATCH * MVALID) return;
    int n = t / MVALID, row = t % MVALID;
    float bv = -3.0e38f;
    int bi = 0;
    #pragma unroll
    for (int sp = 0; sp < NSPLIT; ++sp) {
        size_t o = ((size_t)n * NSPLIT + sp) * MPAD + row;
        float v = g_pval[o];
        if (v > bv) { bv = v; bi = g_pidx[o]; }
    }
    g_idx[n * MPAD + row] = bi;
}

// ---------------------------------------------------------------------------
// L1 + clip + sum: block per (n, position), 128 threads = channels.
// ---------------------------------------------------------------------------
__global__ __launch_bounds__(128) void l1_kernel(const float* __restrict__ outf,
                                                 const float* __restrict__ colf,
                                                 float* __restrict__ d_out) {
    const int pos = blockIdx.x;
    const int n   = blockIdx.y;
    const int c   = threadIdx.x;

    const int i = pos / WP, j = pos % WP;
    const int u = g_idx[n * MPAD + pos];
    const int ui = u / HS, uj = u % HS;

    const float* po = outf + (((size_t)n * CCH + c) * H1 + i) * W1 + j;
    const float* pc = colf + (((size_t)n * CCH + c) * H2 + ui) * W2 + uj;

    float s = 0.0f;
    #pragma unroll
    for (int a = 0; a < 3; ++a)
        #pragma unroll
        for (int b = 0; b < 3; ++b)
            s += fabsf(po[a * W1 + b] - pc[a * W2 + b]);

    #pragma unroll
    for (int off = 16; off; off >>= 1) s += __shfl_xor_sync(0xffffffffu, s, off);

    __shared__ float ws[4];
    if ((threadIdx.x & 31) == 0) ws[threadIdx.x >> 5] = s;
    __syncthreads();
    if (threadIdx.x == 0) {
        float t = ws[0] + ws[1] + ws[2] + ws[3];
        atomicAdd(d_out, fminf(t, 1000.0f));
    }
}

__global__ void zero_out_kernel(float* p) { if (threadIdx.x == 0) p[0] = 0.0f; }

// ---------------------------------------------------------------------------
extern "C" void kernel_launch(void* const* d_in, const int* in_sizes, int n_in,
                              void* d_out, int out_size) {
    const float* outf = (const float*)d_in[0];
    const float* reff = (const float*)d_in[1];
    const float* shpf = (const float*)d_in[2];
    const float* colf = (const float*)d_in[3];
    float* out = (float*)d_out;

    void* pA = nullptr;
    void* pB = nullptr;
    cudaGetSymbolAddress(&pA, g_A);
    cudaGetSymbolAddress(&pB, g_B);

    zero_out_kernel<<<1, 32>>>(out);

    {
        size_t totalA = (size_t)NBATCH * CCH * MPAD;
        pack_patches<<<(int)((totalA + 255) / 256), 256>>>(
            reff, (__nv_bfloat16*)pA, H1, W1, WP, MVALID, MPAD);
        size_t totalB = (size_t)NBATCH * CCH * UPAD;
        pack_patches<<<(int)((totalB + 255) / 256), 256>>>(
            shpf, (__nv_bfloat16*)pB, H2, W2, HS, UVALID, UPAD);
    }

    // GEMM + argmax: grid (31 M-tiles, 5 U-splits, 2 batches) = 310 CTAs
    gemm_argmax_kernel<<<dim3(MPAD / MT, NSPLIT, NBATCH), 256>>>();

    reduce_argmax_kernel<<<(NBATCH * MVALID + 255) / 256, 256>>>();

    l1_kernel<<<dim3(MVALID, NBATCH), 128>>>(outf, colf, out);
}

// round 12
// speedup vs baseline: 1.7906x; 1.2277x over previous
#include <cuda_runtime.h>
#include <cuda_bf16.h>
#include <cstdint>

// ---------------------------------------------------------------------------
// PatchLoss: sim = ref_patches @ shape_patches^T, per-row argmax over U,
// L1(out_patches, color_patch[argmax]) clipped at 1000, summed to scalar.
// N=2, C=128 -> K=1152; M=3844 (pad 3968); U=15876 (pad 16000).
// HMMA mma.sync path (harness ptxas targets sm_103 without 'a'; tcgen05 rejected).
// K layout: k = (a*3+b)*128 + c  (consistent permutation for both operands).
// ---------------------------------------------------------------------------

#define NBATCH 2
#define CCH    128
#define H1     64
#define W1     64
#define H2     128
#define W2     128
#define HP     62
#define WP     62
#define MVALID 3844
#define MPAD   3968           // 31 * 128
#define HS     126
#define UVALID 15876
#define UPAD   16000          // 125 * 128
#define KDIM   1152

// GEMM tiling
#define MT   128
#define NT   128
#define KC   64               // bf16 per K chunk
#define KP   72               // padded row stride (144 B): conflict-free ldmatrix
#define NKI  (KDIM / KC)      // 18
#define NSPLIT 5
#define NT_PER_CTA 25         // 125 / 5
#define NSTAGE 3

#define STAGE_ELEMS (256 * KP)                 // A rows 0..127, B rows 128..255
#define SMEM_BYTES  (NSTAGE * STAGE_ELEMS * 2) // 110592

__device__ __nv_bfloat16 g_A[(size_t)NBATCH * MPAD * KDIM];   // ~18.3 MB
__device__ __nv_bfloat16 g_B[(size_t)NBATCH * UPAD * KDIM];   // ~73.7 MB
__device__ float g_pval[NBATCH * NSPLIT * MPAD];
__device__ int   g_pidx[NBATCH * NSPLIT * MPAD];
__device__ int   g_idx[NBATCH * MPAD];

// ---------------------------------------------------------------------------
// Pack: k = (a*3+b)*CCH + c ; thread = (n, row, c) with c innermost.
// Writes warp-coalesced (64B runs); reads strided but L2-resident.
// ---------------------------------------------------------------------------
__global__ void pack_patches(const float* __restrict__ src,
                             __nv_bfloat16* __restrict__ dst,
                             int Hsrc, int Wsrc, int Wout,
                             int rows_valid, int rows_pad) {
    size_t t = (size_t)blockIdx.x * blockDim.x + threadIdx.x;
    size_t total = (size_t)NBATCH * rows_pad * CCH;
    if (t >= total) return;
    int c   = (int)(t % CCH);
    int row = (int)((t / CCH) % rows_pad);
    int n   = (int)(t / ((size_t)CCH * rows_pad));

    __nv_bfloat16* d = dst + ((size_t)n * rows_pad + row) * KDIM + c;
    if (row >= rows_valid) {
        #pragma unroll
        for (int p = 0; p < 9; ++p) d[p * CCH] = __float2bfloat16(0.0f);
        return;
    }
    int i = row / Wout, j = row % Wout;
    const float* s = src + (((size_t)n * CCH + c) * Hsrc + i) * Wsrc + j;
    #pragma unroll
    for (int a = 0; a < 3; ++a)
        #pragma unroll
        for (int b = 0; b < 3; ++b)
            d[(a * 3 + b) * CCH] = __float2bfloat16(s[a * Wsrc + b]);
}

// ---------------------------------------------------------------------------
__device__ __forceinline__ void cp_async16(uint32_t smem_dst, const void* gmem_src) {
    asm volatile("cp.async.cg.shared.global [%0], [%1], 16;\n"
                 :: "r"(smem_dst), "l"(gmem_src));
}

// ---------------------------------------------------------------------------
// GEMM + argmax: CTA tile 128x128, 3-stage cp.async ring over flattened
// (25 N-tiles x 18 K-chunks) iterations, ONE __syncthreads per chunk.
// 8 warps (2x4), each warp 64x32.
// ---------------------------------------------------------------------------
__global__ __launch_bounds__(256, 2) void gemm_argmax_kernel() {
    extern __shared__ __nv_bfloat16 dyn[];

    const int m0 = blockIdx.x * MT;
    const int sp = blockIdx.y;
    const int n  = blockIdx.z;
    const __nv_bfloat16* Ag = g_A + ((size_t)n * MPAD + m0) * KDIM;
    const __nv_bfloat16* Bg = g_B +
        ((size_t)n * UPAD + (size_t)sp * NT_PER_CTA * NT) * KDIM;

    const int tid  = threadIdx.x;
    const int lane = tid & 31;
    const int wid  = tid >> 5;
    const int wm   = wid >> 2;   // 0..1 -> rows wm*64
    const int wn   = wid & 3;    // 0..3 -> cols wn*32

    const int lrow = lane & 15;
    const int lcol = (lane >> 4) << 3;

    // ---- load-side cursor ---------------------------------------------------
    int l_kt = 0;                      // k-chunk within tile
    const __nv_bfloat16* l_B = Bg;     // current tile B base
    int l_s = 0;                       // stage
    // per-thread chunk coords (4 chunks each for A and B)
    // ch = tid + q*256 ; row = ch>>3 ; k16 = ch&7

    auto issue_stage = [&]() {
        const int k0 = l_kt * KC;
        uint32_t st = (uint32_t)__cvta_generic_to_shared(dyn + l_s * STAGE_ELEMS);
        #pragma unroll
        for (int q = 0; q < 4; ++q) {
            int ch = tid + q * 256;
            int row = ch >> 3, k16 = ch & 7;
            cp_async16(st + (row * KP + k16 * 8) * 2,
                       Ag + (size_t)row * KDIM + k0 + k16 * 8);
        }
        uint32_t stB = st + 128 * KP * 2;
        #pragma unroll
        for (int q = 0; q < 4; ++q) {
            int ch = tid + q * 256;
            int row = ch >> 3, k16 = ch & 7;
            cp_async16(stB + (row * KP + k16 * 8) * 2,
                       l_B + (size_t)row * KDIM + k0 + k16 * 8);
        }
        if (++l_kt == NKI) { l_kt = 0; l_B += (size_t)NT * KDIM; }
        if (++l_s == NSTAGE) l_s = 0;
    };

    // prologue: stages 0,1
    issue_stage();
    asm volatile("cp.async.commit_group;\n" ::: "memory");
    issue_stage();
    asm volatile("cp.async.commit_group;\n" ::: "memory");

    float bestv[8];
    int   besti[8];
    #pragma unroll
    for (int r = 0; r < 8; ++r) { bestv[r] = -3.0e38f; besti[r] = 0; }

    float acc[4][4][4];
    int c_kt = 0, c_nt = 0, c_s = 0;

    const int TOTAL = NT_PER_CTA * NKI;   // 450
    for (int it = 0; it < TOTAL; ++it) {
        if (c_kt == 0) {
            #pragma unroll
            for (int mi = 0; mi < 4; ++mi)
                #pragma unroll
                for (int ni = 0; ni < 4; ++ni)
                    #pragma unroll
                    for (int q = 0; q < 4; ++q) acc[mi][ni][q] = 0.0f;
        }

        asm volatile("cp.async.wait_group 1;\n" ::: "memory");
        __syncthreads();

        if (it + 2 < TOTAL) issue_stage();
        asm volatile("cp.async.commit_group;\n" ::: "memory");

        const __nv_bfloat16* sA = dyn + c_s * STAGE_ELEMS;
        const __nv_bfloat16* sB = sA + 128 * KP;

        #pragma unroll
        for (int kk = 0; kk < 4; ++kk) {
            uint32_t af[4][4], bf[4][2];
            #pragma unroll
            for (int mi = 0; mi < 4; ++mi) {
                uint32_t addr = (uint32_t)__cvta_generic_to_shared(
                    sA + (wm * 64 + mi * 16 + lrow) * KP + kk * 16 + lcol);
                asm volatile("ldmatrix.sync.aligned.m8n8.x4.shared.b16 {%0,%1,%2,%3}, [%4];"
                    : "=r"(af[mi][0]), "=r"(af[mi][1]), "=r"(af[mi][2]), "=r"(af[mi][3])
                    : "r"(addr));
            }
            #pragma unroll
            for (int nh = 0; nh < 2; ++nh) {
                uint32_t r0, r1, r2, r3;
                uint32_t addr = (uint32_t)__cvta_generic_to_shared(
                    sB + (wn * 32 + nh * 16 + lrow) * KP + kk * 16 + lcol);
                asm volatile("ldmatrix.sync.aligned.m8n8.x4.shared.b16 {%0,%1,%2,%3}, [%4];"
                    : "=r"(r0), "=r"(r1), "=r"(r2), "=r"(r3) : "r"(addr));
                bf[nh * 2 + 0][0] = r0; bf[nh * 2 + 0][1] = r2;
                bf[nh * 2 + 1][0] = r1; bf[nh * 2 + 1][1] = r3;
            }
            #pragma unroll
            for (int mi = 0; mi < 4; ++mi)
                #pragma unroll
                for (int ni = 0; ni < 4; ++ni)
                    asm volatile(
                        "mma.sync.aligned.m16n8k16.row.col.f32.bf16.bf16.f32 "
                        "{%0,%1,%2,%3}, {%4,%5,%6,%7}, {%8,%9}, {%0,%1,%2,%3};"
                        : "+f"(acc[mi][ni][0]), "+f"(acc[mi][ni][1]),
                          "+f"(acc[mi][ni][2]), "+f"(acc[mi][ni][3])
                        : "r"(af[mi][0]), "r"(af[mi][1]), "r"(af[mi][2]), "r"(af[mi][3]),
                          "r"(bf[ni][0]), "r"(bf[ni][1]));
        }

        if (++c_s == NSTAGE) c_s = 0;

        if (++c_kt == NKI) {
            c_kt = 0;
            // argmax update for finished tile c_nt (mask padded u)
            const int ubase = (sp * NT_PER_CTA + c_nt) * NT + wn * 32 + (lane & 3) * 2;
            #pragma unroll
            for (int mi = 0; mi < 4; ++mi)
                #pragma unroll
                for (int rh = 0; rh < 2; ++rh) {
                    const int r = mi * 2 + rh;
                    #pragma unroll
                    for (int ni = 0; ni < 4; ++ni)
                        #pragma unroll
                        for (int ch = 0; ch < 2; ++ch) {
                            int u = ubase + ni * 8 + ch;
                            float v = acc[mi][ni][rh * 2 + ch];
                            if (u < UVALID && v > bestv[r]) { bestv[r] = v; besti[r] = u; }
                        }
                }
            ++c_nt;
        }
    }

    // quad reduction (cols within warp)
    #pragma unroll
    for (int r = 0; r < 8; ++r) {
        #pragma unroll
        for (int off = 1; off <= 2; off <<= 1) {
            float ov = __shfl_xor_sync(0xffffffffu, bestv[r], off);
            int   oi = __shfl_xor_sync(0xffffffffu, besti[r], off);
            if (ov > bestv[r] || (ov == bestv[r] && oi < besti[r])) {
                bestv[r] = ov; besti[r] = oi;
            }
        }
    }

    // cross-warp reduction through smem (alias stage 0 — dead now)
    __syncthreads();
    float* s_val = (float*)dyn;             // [4][MT]
    int*   s_idx = (int*)(s_val + 4 * MT);  // [4][MT]
    if ((lane & 3) == 0) {
        #pragma unroll
        for (int r = 0; r < 8; ++r) {
            int mi = r >> 1, rh = r & 1;
            int row = wm * 64 + mi * 16 + rh * 8 + (lane >> 2);
            s_val[wn * MT + row] = bestv[r];
            s_idx[wn * MT + row] = besti[r];
        }
    }
    __syncthreads();
    if (tid < MT) {
        float bv = s_val[tid];
        int   bi = s_idx[tid];
        #pragma unroll
        for (int w = 1; w < 4; ++w) {
            float ov = s_val[w * MT + tid];
            int   oi = s_idx[w * MT + tid];
            if (ov > bv || (ov == bv && oi < bi)) { bv = ov; bi = oi; }
        }
        if (m0 + tid < MVALID) {
            const size_t o = ((size_t)n * NSPLIT + sp) * MPAD + m0 + tid;
            g_pval[o] = bv;
            g_pidx[o] = bi;
        }
    }
}

// ---------------------------------------------------------------------------
// Combine split partials (ascending split = ascending u -> first-max kept).
// ---------------------------------------------------------------------------
__global__ void reduce_argmax_kernel() {
    int t = blockIdx.x * blockDim.x + threadIdx.x;
    if (t >= NBATCH * MVALID) return;
    int n = t / MVALID, row = t % MVALID;
    float bv = -3.0e38f;
    int bi = 0;
    #pragma unroll
    for (int sp = 0; sp < NSPLIT; ++sp) {
        size_t o = ((size_t)n * NSPLIT + sp) * MPAD + row;
        float v = g_pval[o];
        if (v > bv) { bv = v; bi = g_pidx[o]; }
    }
    g_idx[n * MPAD + row] = bi;
}

// ---------------------------------------------------------------------------
// L1 + clip + sum: block per (n, position), 128 threads = channels.
// ---------------------------------------------------------------------------
__global__ __launch_bounds__(128) void l1_kernel(const float* __restrict__ outf,
                                                 const float* __restrict__ colf,
                                                 float* __restrict__ d_out) {
    const int pos = blockIdx.x;
    const int n   = blockIdx.y;
    const int c   = threadIdx.x;

    const int i = pos / WP, j = pos % WP;
    const int u = g_idx[n * MPAD + pos];
    const int ui = u / HS, uj = u % HS;

    const float* po = outf + (((size_t)n * CCH + c) * H1 + i) * W1 + j;
    const float* pc = colf + (((size_t)n * CCH + c) * H2 + ui) * W2 + uj;

    float s = 0.0f;
    #pragma unroll
    for (int a = 0; a < 3; ++a)
        #pragma unroll
        for (int b = 0; b < 3; ++b)
            s += fabsf(po[a * W1 + b] - pc[a * W2 + b]);

    #pragma unroll
    for (int off = 16; off; off >>= 1) s += __shfl_xor_sync(0xffffffffu, s, off);

    __shared__ float ws[4];
    if ((threadIdx.x & 31) == 0) ws[threadIdx.x >> 5] = s;
    __syncthreads();
    if (threadIdx.x == 0) {
        float t = ws[0] + ws[1] + ws[2] + ws[3];
        atomicAdd(d_out, fminf(t, 1000.0f));
    }
}

__global__ void zero_out_kernel(float* p) { if (threadIdx.x == 0) p[0] = 0.0f; }

// ---------------------------------------------------------------------------
extern "C" void kernel_launch(void* const* d_in, const int* in_sizes, int n_in,
                              void* d_out, int out_size) {
    const float* outf = (const float*)d_in[0];
    const float* reff = (const float*)d_in[1];
    const float* shpf = (const float*)d_in[2];
    const float* colf = (const float*)d_in[3];
    float* out = (float*)d_out;

    cudaFuncSetAttribute(gemm_argmax_kernel,
                         cudaFuncAttributeMaxDynamicSharedMemorySize, SMEM_BYTES);

    void* pA = nullptr;
    void* pB = nullptr;
    cudaGetSymbolAddress(&pA, g_A);
    cudaGetSymbolAddress(&pB, g_B);

    zero_out_kernel<<<1, 32>>>(out);

    {
        size_t totalA = (size_t)NBATCH * CCH * MPAD;
        pack_patches<<<(int)((totalA + 255) / 256), 256>>>(
            reff, (__nv_bfloat16*)pA, H1, W1, WP, MVALID, MPAD);
        size_t totalB = (size_t)NBATCH * CCH * UPAD;
        pack_patches<<<(int)((totalB + 255) / 256), 256>>>(
            shpf, (__nv_bfloat16*)pB, H2, W2, HS, UVALID, UPAD);
    }

    // GEMM + argmax: grid (31 M-tiles, 5 U-splits, 2 batches) = 310 CTAs
    gemm_argmax_kernel<<<dim3(MPAD / MT, NSPLIT, NBATCH), 256, SMEM_BYTES>>>();

    reduce_argmax_kernel<<<(NBATCH * MVALID + 255) / 256, 256>>>();

    l1_kernel<<<dim3(MVALID, NBATCH), 128>>>(outf, colf, out);
}

// round 14
// speedup vs baseline: 2.4531x; 1.3700x over previous
#include <cuda_runtime.h>
#include <cuda_bf16.h>
#include <cstdint>

// ---------------------------------------------------------------------------
// PatchLoss: sim = ref_patches @ shape_patches^T, per-row argmax over U,
// L1(out_patches, color_patch[argmax]) clipped at 1000, summed to scalar.
// N=2, C=128 -> K=1152; M=3844 (pad 3968); U=15876 (pad 16000).
// HMMA mma.sync path (harness ptxas targets sm_103 without 'a').
// K layout: k = (a*3+b)*128 + c  (consistent permutation for both operands).
// ---------------------------------------------------------------------------

#define NBATCH 2
#define CCH    128
#define H1     64
#define W1     64
#define H2     128
#define W2     128
#define HP     62
#define WP     62
#define MVALID 3844
#define MPAD   3968           // 31 * 128
#define HS     126
#define UVALID 15876
#define UPAD   16000          // 125 * 128
#define KDIM   1152

// GEMM tiling
#define MT   128
#define NT   128
#define KC   64               // bf16 per K chunk
#define KP   72               // padded row stride (144 B): conflict-free ldmatrix
#define NKI  (KDIM / KC)      // 18
#define NSPLIT 25
#define NT_PER_CTA 5          // 125 / 25
#define NSTAGE 3

#define STAGE_ELEMS (256 * KP)                 // A rows 0..127, B rows 128..255
#define SMEM_BYTES  (NSTAGE * STAGE_ELEMS * 2) // 110592

__device__ __nv_bfloat16 g_A[(size_t)NBATCH * MPAD * KDIM];   // ~18.3 MB
__device__ __nv_bfloat16 g_B[(size_t)NBATCH * UPAD * KDIM];   // ~73.7 MB
__device__ float g_pval[NBATCH * NSPLIT * MPAD];
__device__ int   g_pidx[NBATCH * NSPLIT * MPAD];
__device__ int   g_idx[NBATCH * MPAD];

// ---------------------------------------------------------------------------
// Pack: k = (a*3+b)*CCH + c ; thread = (n, row, c) with c innermost.
// ---------------------------------------------------------------------------
__global__ void pack_patches(const float* __restrict__ src,
                             __nv_bfloat16* __restrict__ dst,
                             int Hsrc, int Wsrc, int Wout,
                             int rows_valid, int rows_pad) {
    size_t t = (size_t)blockIdx.x * blockDim.x + threadIdx.x;
    size_t total = (size_t)NBATCH * rows_pad * CCH;
    if (t >= total) return;
    int c   = (int)(t % CCH);
    int row = (int)((t / CCH) % rows_pad);
    int n   = (int)(t / ((size_t)CCH * rows_pad));

    __nv_bfloat16* d = dst + ((size_t)n * rows_pad + row) * KDIM + c;
    if (row >= rows_valid) {
        #pragma unroll
        for (int p = 0; p < 9; ++p) d[p * CCH] = __float2bfloat16(0.0f);
        return;
    }
    int i = row / Wout, j = row % Wout;
    const float* s = src + (((size_t)n * CCH + c) * Hsrc + i) * Wsrc + j;
    #pragma unroll
    for (int a = 0; a < 3; ++a)
        #pragma unroll
        for (int b = 0; b < 3; ++b)
            d[(a * 3 + b) * CCH] = __float2bfloat16(s[a * Wsrc + b]);
}

// ---------------------------------------------------------------------------
__device__ __forceinline__ void cp_async16(uint32_t smem_dst, const void* gmem_src) {
    asm volatile("cp.async.cg.shared.global [%0], [%1], 16;\n"
                 :: "r"(smem_dst), "l"(gmem_src));
}

// ---------------------------------------------------------------------------
// GEMM + argmax: CTA tile 128x128, 4 warps (2x2), warp tile 64x64.
// 3-stage cp.async ring over flattened (5 N-tiles x 18 K-chunks), one
// __syncthreads per chunk. Per-row running (max,idx) partials.
// ---------------------------------------------------------------------------
__global__ __launch_bounds__(128, 2) void gemm_argmax_kernel() {
    extern __shared__ __nv_bfloat16 dyn[];

    const int m0 = blockIdx.x * MT;
    const int sp = blockIdx.y;
    const int n  = blockIdx.z;
    const __nv_bfloat16* Ag = g_A + ((size_t)n * MPAD + m0) * KDIM;
    const __nv_bfloat16* Bg = g_B +
        ((size_t)n * UPAD + (size_t)sp * NT_PER_CTA * NT) * KDIM;

    const int tid  = threadIdx.x;
    const int lane = tid & 31;
    const int wid  = tid >> 5;
    const int wm   = wid >> 1;   // 0..1 -> rows wm*64
    const int wn   = wid & 1;    // 0..1 -> cols wn*64

    const int lrow = lane & 15;
    const int lcol = (lane >> 4) << 3;

    // ---- load-side cursor ---------------------------------------------------
    int l_kt = 0;
    const __nv_bfloat16* l_B = Bg;
    int l_s = 0;

    auto issue_stage = [&]() {
        const int k0 = l_kt * KC;
        uint32_t st = (uint32_t)__cvta_generic_to_shared(dyn + l_s * STAGE_ELEMS);
        #pragma unroll
        for (int q = 0; q < 8; ++q) {
            int ch = tid + q * 128;
            int row = ch >> 3, k16 = ch & 7;
            cp_async16(st + (row * KP + k16 * 8) * 2,
                       Ag + (size_t)row * KDIM + k0 + k16 * 8);
        }
        uint32_t stB = st + 128 * KP * 2;
        #pragma unroll
        for (int q = 0; q < 8; ++q) {
            int ch = tid + q * 128;
            int row = ch >> 3, k16 = ch & 7;
            cp_async16(stB + (row * KP + k16 * 8) * 2,
                       l_B + (size_t)row * KDIM + k0 + k16 * 8);
        }
        if (++l_kt == NKI) { l_kt = 0; l_B += (size_t)NT * KDIM; }
        if (++l_s == NSTAGE) l_s = 0;
    };

    issue_stage();
    asm volatile("cp.async.commit_group;\n" ::: "memory");
    issue_stage();
    asm volatile("cp.async.commit_group;\n" ::: "memory");

    float bestv[8];
    int   besti[8];
    #pragma unroll
    for (int r = 0; r < 8; ++r) { bestv[r] = -3.0e38f; besti[r] = 0; }

    float acc[4][8][4];        // [mi 16-row][ni 8-col][quad]
    int c_kt = 0, c_nt = 0, c_s = 0;

    const int TOTAL = NT_PER_CTA * NKI;   // 90
    for (int it = 0; it < TOTAL; ++it) {
        if (c_kt == 0) {
            #pragma unroll
            for (int mi = 0; mi < 4; ++mi)
                #pragma unroll
                for (int ni = 0; ni < 8; ++ni)
                    #pragma unroll
                    for (int q = 0; q < 4; ++q) acc[mi][ni][q] = 0.0f;
        }

        asm volatile("cp.async.wait_group 1;\n" ::: "memory");
        __syncthreads();

        if (it + 2 < TOTAL) issue_stage();
        asm volatile("cp.async.commit_group;\n" ::: "memory");

        const __nv_bfloat16* sA = dyn + c_s * STAGE_ELEMS;
        const __nv_bfloat16* sB = sA + 128 * KP;

        #pragma unroll
        for (int kk = 0; kk < 4; ++kk) {
            uint32_t af[4][4], bf[8][2];
            #pragma unroll
            for (int mi = 0; mi < 4; ++mi) {
                uint32_t addr = (uint32_t)__cvta_generic_to_shared(
                    sA + (wm * 64 + mi * 16 + lrow) * KP + kk * 16 + lcol);
                asm volatile("ldmatrix.sync.aligned.m8n8.x4.shared.b16 {%0,%1,%2,%3}, [%4];"
                    : "=r"(af[mi][0]), "=r"(af[mi][1]), "=r"(af[mi][2]), "=r"(af[mi][3])
                    : "r"(addr));
            }
            #pragma unroll
            for (int nh = 0; nh < 4; ++nh) {
                uint32_t r0, r1, r2, r3;
                uint32_t addr = (uint32_t)__cvta_generic_to_shared(
                    sB + (wn * 64 + nh * 16 + lrow) * KP + kk * 16 + lcol);
                asm volatile("ldmatrix.sync.aligned.m8n8.x4.shared.b16 {%0,%1,%2,%3}, [%4];"
                    : "=r"(r0), "=r"(r1), "=r"(r2), "=r"(r3) : "r"(addr));
                bf[nh * 2 + 0][0] = r0; bf[nh * 2 + 0][1] = r2;
                bf[nh * 2 + 1][0] = r1; bf[nh * 2 + 1][1] = r3;
            }
            #pragma unroll
            for (int mi = 0; mi < 4; ++mi)
                #pragma unroll
                for (int ni = 0; ni < 8; ++ni)
                    asm volatile(
                        "mma.sync.aligned.m16n8k16.row.col.f32.bf16.bf16.f32 "
                        "{%0,%1,%2,%3}, {%4,%5,%6,%7}, {%8,%9}, {%0,%1,%2,%3};"
                        : "+f"(acc[mi][ni][0]), "+f"(acc[mi][ni][1]),
                          "+f"(acc[mi][ni][2]), "+f"(acc[mi][ni][3])
                        : "r"(af[mi][0]), "r"(af[mi][1]), "r"(af[mi][2]), "r"(af[mi][3]),
                          "r"(bf[ni][0]), "r"(bf[ni][1]));
        }

        if (++c_s == NSTAGE) c_s = 0;

        if (++c_kt == NKI) {
            c_kt = 0;
            const int ubase = (sp * NT_PER_CTA + c_nt) * NT + wn * 64 + (lane & 3) * 2;
            #pragma unroll
            for (int mi = 0; mi < 4; ++mi)
                #pragma unroll
                for (int rh = 0; rh < 2; ++rh) {
                    const int r = mi * 2 + rh;
                    #pragma unroll
                    for (int ni = 0; ni < 8; ++ni)
                        #pragma unroll
                        for (int ch = 0; ch < 2; ++ch) {
                            int u = ubase + ni * 8 + ch;
                            float v = acc[mi][ni][rh * 2 + ch];
                            if (u < UVALID && v > bestv[r]) { bestv[r] = v; besti[r] = u; }
                        }
                }
            ++c_nt;
        }
    }

    // quad reduction (cols within warp)
    #pragma unroll
    for (int r = 0; r < 8; ++r) {
        #pragma unroll
        for (int off = 1; off <= 2; off <<= 1) {
            float ov = __shfl_xor_sync(0xffffffffu, bestv[r], off);
            int   oi = __shfl_xor_sync(0xffffffffu, besti[r], off);
            if (ov > bestv[r] || (ov == bestv[r] && oi < besti[r])) {
                bestv[r] = ov; besti[r] = oi;
            }
        }
    }

    // cross-warp reduction through smem (alias stage 0 — dead now)
    __syncthreads();
    float* s_val = (float*)dyn;             // [2][MT]
    int*   s_idx = (int*)(s_val + 2 * MT);  // [2][MT]
    if ((lane & 3) == 0) {
        #pragma unroll
        for (int r = 0; r < 8; ++r) {
            int mi = r >> 1, rh = r & 1;
            int row = wm * 64 + mi * 16 + rh * 8 + (lane >> 2);
            s_val[wn * MT + row] = bestv[r];
            s_idx[wn * MT + row] = besti[r];
        }
    }
    __syncthreads();
    if (tid < MT) {
        float bv = s_val[tid];
        int   bi = s_idx[tid];
        float ov = s_val[MT + tid];
        int   oi = s_idx[MT + tid];
        if (ov > bv || (ov == bv && oi < bi)) { bv = ov; bi = oi; }
        if (m0 + tid < MVALID) {
            const size_t o = ((size_t)n * NSPLIT + sp) * MPAD + m0 + tid;
            g_pval[o] = bv;
            g_pidx[o] = bi;
        }
    }
}

// ---------------------------------------------------------------------------
// Combine split partials (ascending split = ascending u -> first-max kept).
// ---------------------------------------------------------------------------
__global__ void reduce_argmax_kernel() {
    int t = blockIdx.x * blockDim.x + threadIdx.x;
    if (t >= NBATCH * MVALID) return;
    int n = t / MVALID, row = t % MVALID;
    float bv = -3.0e38f;
    int bi = 0;
    #pragma unroll
    for (int sp = 0; sp < NSPLIT; ++sp) {
        size_t o = ((size_t)n * NSPLIT + sp) * MPAD + row;
        float v = g_pval[o];
        if (v > bv) { bv = v; bi = g_pidx[o]; }
    }
    g_idx[n * MPAD + row] = bi;
}

// ---------------------------------------------------------------------------
// L1 + clip + sum: block per (n, position), 128 threads = channels.
// ---------------------------------------------------------------------------
__global__ __launch_bounds__(128) void l1_kernel(const float* __restrict__ outf,
                                                 const float* __restrict__ colf,
                                                 float* __restrict__ d_out) {
    const int pos = blockIdx.x;
    const int n   = blockIdx.y;
    const int c   = threadIdx.x;

    const int i = pos / WP, j = pos % WP;
    const int u = g_idx[n * MPAD + pos];
    const int ui = u / HS, uj = u % HS;

    const float* po = outf + (((size_t)n * CCH + c) * H1 + i) * W1 + j;
    const float* pc = colf + (((size_t)n * CCH + c) * H2 + ui) * W2 + uj;

    float s = 0.0f;
    #pragma unroll
    for (int a = 0; a < 3; ++a)
        #pragma unroll
        for (int b = 0; b < 3; ++b)
            s += fabsf(po[a * W1 + b] - pc[a * W2 + b]);

    #pragma unroll
    for (int off = 16; off; off >>= 1) s += __shfl_xor_sync(0xffffffffu, s, off);

    __shared__ float ws[4];
    if ((threadIdx.x & 31) == 0) ws[threadIdx.x >> 5] = s;
    __syncthreads();
    if (threadIdx.x == 0) {
        float t = ws[0] + ws[1] + ws[2] + ws[3];
        atomicAdd(d_out, fminf(t, 1000.0f));
    }
}

__global__ void zero_out_kernel(float* p) { if (threadIdx.x == 0) p[0] = 0.0f; }

// ---------------------------------------------------------------------------
extern "C" void kernel_launch(void* const* d_in, const int* in_sizes, int n_in,
                              void* d_out, int out_size) {
    const float* outf = (const float*)d_in[0];
    const float* reff = (const float*)d_in[1];
    const float* shpf = (const float*)d_in[2];
    const float* colf = (const float*)d_in[3];
    float* out = (float*)d_out;

    cudaFuncSetAttribute(gemm_argmax_kernel,
                         cudaFuncAttributeMaxDynamicSharedMemorySize, SMEM_BYTES);

    void* pA = nullptr;
    void* pB = nullptr;
    cudaGetSymbolAddress(&pA, g_A);
    cudaGetSymbolAddress(&pB, g_B);

    zero_out_kernel<<<1, 32>>>(out);

    {
        size_t totalA = (size_t)NBATCH * CCH * MPAD;
        pack_patches<<<(int)((totalA + 255) / 256), 256>>>(
            reff, (__nv_bfloat16*)pA, H1, W1, WP, MVALID, MPAD);
        size_t totalB = (size_t)NBATCH * CCH * UPAD;
        pack_patches<<<(int)((totalB + 255) / 256), 256>>>(
            shpf, (__nv_bfloat16*)pB, H2, W2, HS, UVALID, UPAD);
    }

    // GEMM + argmax: grid (31 M-tiles, 25 U-splits, 2 batches) = 1550 CTAs
    gemm_argmax_kernel<<<dim3(MPAD / MT, NSPLIT, NBATCH), 128, SMEM_BYTES>>>();

    reduce_argmax_kernel<<<(NBATCH * MVALID + 255) / 256, 256>>>();

    l1_kernel<<<dim3(MVALID, NBATCH), 128>>>(outf, colf, out);
}

// round 15
// speedup vs baseline: 4.2095x; 1.7160x over previous
#include <cuda_runtime.h>
#include <cuda_bf16.h>
#include <cstdint>

// ---------------------------------------------------------------------------
// PatchLoss via diagonal-sliced correlation:
//   E[(s,vs)][j,uj] = sum_{b,c} ref[c,s,j+b] * shape[c,vs,uj+b]   (K=384 GEMM)
//   sim[(i,j),(ui,uj)] = sum_a E[(i+a, ui+a)][j,uj]               (frag adds)
// argmax over (ui,uj) per anchor, then L1(out, color[argmax]) clip 1000, sum.
// 2.7x fewer tensor FLOPs than the full K=1152 patch GEMM.
// ---------------------------------------------------------------------------

#define NBATCH 2
#define CCH    128
#define H1     64
#define W1     64
#define H2     128
#define W2     128
#define WP     62
#define MVALID 3844
#define HS     126
#define KE     384            // 3 * 128
#define NDIAG  187            // d = ui - i in [-61, 125]
#define TI     16             // anchors per CTA chunk
#define KCH    64             // k per pipeline chunk
#define NKCH   6              // 384/64
#define KP     72             // padded smem row stride (144 B)
#define NSTAGE 3

#define STAGE_ELEMS (192 * KP)                  // 64 Xe rows + 128 Ye rows
#define SMEM_BYTES  (NSTAGE * STAGE_ELEMS * 2)  // 82944

__device__ __nv_bfloat16 g_Xe[(size_t)NBATCH * 64 * 64 * KE];     // 6.3 MB
__device__ __nv_bfloat16 g_Ye[(size_t)NBATCH * 128 * 128 * KE];   // 25 MB
__device__ float g_pval[(size_t)NBATCH * NDIAG * MVALID];
__device__ int   g_pidx[(size_t)NBATCH * NDIAG * MVALID];
__device__ int   g_idx[NBATCH * MVALID];

// ---------------------------------------------------------------------------
// Pack Xe[n][s][j][b*128+c] = bf16(ref[n,c,s,j+b]), zero for j+b > 63.
// Layout == linear thread index (c innermost -> coalesced writes).
// ---------------------------------------------------------------------------
__global__ void pack_xe(const float* __restrict__ ref) {
    size_t t = (size_t)blockIdx.x * blockDim.x + threadIdx.x;
    if (t >= (size_t)NBATCH * 64 * 64 * KE) return;
    int c = (int)(t % CCH);
    int b = (int)((t / CCH) % 3);
    int j = (int)((t / KE) % 64);
    int s = (int)((t / ((size_t)KE * 64)) % 64);
    int n = (int)(t / ((size_t)KE * 64 * 64));
    float v = (j + b < W1)
        ? ref[(((size_t)n * CCH + c) * H1 + s) * W1 + j + b] : 0.0f;
    g_Xe[t] = __float2bfloat16(v);
}

// Ye[n][vs][uj][b*128+c] = bf16(shape[n,c,vs,uj+b]), zero for uj+b > 127.
__global__ void pack_ye(const float* __restrict__ shp) {
    size_t t = (size_t)blockIdx.x * blockDim.x + threadIdx.x;
    if (t >= (size_t)NBATCH * 128 * 128 * KE) return;
    int c  = (int)(t % CCH);
    int b  = (int)((t / CCH) % 3);
    int uj = (int)((t / KE) % 128);
    int vs = (int)((t / ((size_t)KE * 128)) % 128);
    int n  = (int)(t / ((size_t)KE * 128 * 128));
    float v = (uj + b < W2)
        ? shp[(((size_t)n * CCH + c) * H2 + vs) * W2 + uj + b] : 0.0f;
    g_Ye[t] = __float2bfloat16(v);
}

// ---------------------------------------------------------------------------
__device__ __forceinline__ void cp_async16(uint32_t smem_dst, const void* gmem_src) {
    asm volatile("cp.async.cg.shared.global [%0], [%1], 16;\n"
                 :: "r"(smem_dst), "l"(gmem_src));
}

// ---------------------------------------------------------------------------
// Diagonal-chain GEMM + stencil + argmax.
// Grid (NDIAG, 4 chunks, NBATCH). 256 threads = 8 warps (2 wm x 4 wn),
// warp tile 32j x 32uj per slice. Register rings P0/P1 hold partial a-sums.
// ---------------------------------------------------------------------------
__global__ __launch_bounds__(256, 1) void simdiag_kernel() {
    extern __shared__ __nv_bfloat16 dyn[];
    __shared__ float sv[4 * 64];
    __shared__ int   si[4 * 64];

    const int dIdx = blockIdx.x;
    const int d    = dIdx - 61;
    const int n    = blockIdx.z;

    int i_lo = blockIdx.y * TI;
    if (-d > i_lo) i_lo = -d;
    int i_hi = blockIdx.y * TI + TI - 1;
    if (i_hi > 61) i_hi = 61;
    if (i_hi > 125 - d) i_hi = 125 - d;
    if (i_lo > i_hi) return;

    const int nsl   = i_hi + 3 - i_lo;      // slices s = i_lo .. i_hi+2
    const int TOTAL = nsl * NKCH;

    const __nv_bfloat16* Xb = g_Xe + ((size_t)n * 64 + i_lo) * 64 * KE;
    const __nv_bfloat16* Yb = g_Ye + ((size_t)n * 128 + (i_lo + d)) * 128 * KE;

    const int tid  = threadIdx.x;
    const int lane = tid & 31;
    const int wid  = tid >> 5;
    const int wm   = wid >> 2;   // 0..1 -> j rows wm*32
    const int wn   = wid & 3;    // 0..3 -> uj cols wn*32
    const int lrow = lane & 15;
    const int lcol = (lane >> 4) << 3;

    int l_sl = 0, l_kc = 0, l_s = 0;
    auto issue_stage = [&]() {
        const int k0 = l_kc * KCH;
        uint32_t st = (uint32_t)__cvta_generic_to_shared(dyn + l_s * STAGE_ELEMS);
        const __nv_bfloat16* xs = Xb + (size_t)l_sl * 64 * KE + k0;
        const __nv_bfloat16* ys = Yb + (size_t)l_sl * 128 * KE + k0;
        #pragma unroll
        for (int q = 0; q < 2; ++q) {
            int ch = tid + q * 256;
            int row = ch >> 3, k16 = ch & 7;
            cp_async16(st + (row * KP + k16 * 8) * 2,
                       xs + (size_t)row * KE + k16 * 8);
        }
        #pragma unroll
        for (int q = 0; q < 4; ++q) {
            int ch = tid + q * 256;
            int row = ch >> 3, k16 = ch & 7;
            cp_async16(st + ((64 + row) * KP + k16 * 8) * 2,
                       ys + (size_t)row * KE + k16 * 8);
        }
        if (++l_kc == NKCH) { l_kc = 0; ++l_sl; }
        if (++l_s == NSTAGE) l_s = 0;
    };

    issue_stage();
    asm volatile("cp.async.commit_group;\n" ::: "memory");
    issue_stage();
    asm volatile("cp.async.commit_group;\n" ::: "memory");

    float acc[2][4][4], P0[2][4][4], P1[2][4][4];
    #pragma unroll
    for (int mi = 0; mi < 2; ++mi)
        #pragma unroll
        for (int ni = 0; ni < 4; ++ni)
            #pragma unroll
            for (int q = 0; q < 4; ++q) { P0[mi][ni][q] = 0.0f; P1[mi][ni][q] = 0.0f; }

    int c_kc = 0, c_sl = 0, c_s = 0;
    for (int it = 0; it < TOTAL; ++it) {
        if (c_kc == 0) {
            #pragma unroll
            for (int mi = 0; mi < 2; ++mi)
                #pragma unroll
                for (int ni = 0; ni < 4; ++ni)
                    #pragma unroll
                    for (int q = 0; q < 4; ++q) acc[mi][ni][q] = 0.0f;
        }

        asm volatile("cp.async.wait_group 1;\n" ::: "memory");
        __syncthreads();

        if (it + 2 < TOTAL) issue_stage();
        asm volatile("cp.async.commit_group;\n" ::: "memory");

        const __nv_bfloat16* sA = dyn + c_s * STAGE_ELEMS;

        #pragma unroll
        for (int kk = 0; kk < 4; ++kk) {
            uint32_t af[2][4], bf[4][2];
            #pragma unroll
            for (int mi = 0; mi < 2; ++mi) {
                uint32_t addr = (uint32_t)__cvta_generic_to_shared(
                    sA + (wm * 32 + mi * 16 + lrow) * KP + kk * 16 + lcol);
                asm volatile("ldmatrix.sync.aligned.m8n8.x4.shared.b16 {%0,%1,%2,%3}, [%4];"
                    : "=r"(af[mi][0]), "=r"(af[mi][1]), "=r"(af[mi][2]), "=r"(af[mi][3])
                    : "r"(addr));
            }
            #pragma unroll
            for (int nh = 0; nh < 2; ++nh) {
                uint32_t r0, r1, r2, r3;
                uint32_t addr = (uint32_t)__cvta_generic_to_shared(
                    sA + (64 + wn * 32 + nh * 16 + lrow) * KP + kk * 16 + lcol);
                asm volatile("ldmatrix.sync.aligned.m8n8.x4.shared.b16 {%0,%1,%2,%3}, [%4];"
                    : "=r"(r0), "=r"(r1), "=r"(r2), "=r"(r3) : "r"(addr));
                bf[nh * 2 + 0][0] = r0; bf[nh * 2 + 0][1] = r2;
                bf[nh * 2 + 1][0] = r1; bf[nh * 2 + 1][1] = r3;
            }
            #pragma unroll
            for (int mi = 0; mi < 2; ++mi)
                #pragma unroll
                for (int ni = 0; ni < 4; ++ni)
                    asm volatile(
                        "mma.sync.aligned.m16n8k16.row.col.f32.bf16.bf16.f32 "
                        "{%0,%1,%2,%3}, {%4,%5,%6,%7}, {%8,%9}, {%0,%1,%2,%3};"
                        : "+f"(acc[mi][ni][0]), "+f"(acc[mi][ni][1]),
                          "+f"(acc[mi][ni][2]), "+f"(acc[mi][ni][3])
                        : "r"(af[mi][0]), "r"(af[mi][1]), "r"(af[mi][2]), "r"(af[mi][3]),
                          "r"(bf[ni][0]), "r"(bf[ni][1]));
        }

        if (++c_s == NSTAGE) c_s = 0;

        if (++c_kc == NKCH) {
            c_kc = 0;
            const int s = i_lo + c_sl;

            if (s >= i_lo + 2) {
                // anchor i = s-2 completes: sim = P0 + acc; fused argmax over uj
                const int ianc = s - 2;
                const int ui   = ianc + d;
                #pragma unroll
                for (int mi = 0; mi < 2; ++mi)
                    #pragma unroll
                    for (int rh = 0; rh < 2; ++rh) {
                        float bv = -3.0e38f; int bu = 0;
                        #pragma unroll
                        for (int ni = 0; ni < 4; ++ni)
                            #pragma unroll
                            for (int ch = 0; ch < 2; ++ch) {
                                int uj = wn * 32 + ni * 8 + (lane & 3) * 2 + ch;
                                float v = P0[mi][ni][rh * 2 + ch] + acc[mi][ni][rh * 2 + ch];
                                if (uj < HS && v > bv) { bv = v; bu = uj; }
                            }
                        #pragma unroll
                        for (int off = 1; off <= 2; off <<= 1) {
                            float ov = __shfl_xor_sync(0xffffffffu, bv, off);
                            int   ou = __shfl_xor_sync(0xffffffffu, bu, off);
                            if (ov > bv || (ov == bv && ou < bu)) { bv = ov; bu = ou; }
                        }
                        if ((lane & 3) == 0) {
                            int row = wm * 32 + mi * 16 + rh * 8 + (lane >> 2);
                            sv[wn * 64 + row] = bv;
                            si[wn * 64 + row] = bu;
                        }
                    }
                __syncthreads();
                if (tid < 64) {
                    int j = tid;
                    float bv = sv[j]; int bu = si[j];
                    #pragma unroll
                    for (int w = 1; w < 4; ++w) {
                        float ov = sv[w * 64 + j];
                        int   ou = si[w * 64 + j];
                        if (ov > bv || (ov == bv && ou < bu)) { bv = ov; bu = ou; }
                    }
                    if (j < WP) {
                        size_t o = ((size_t)n * NDIAG + dIdx) * MVALID + ianc * WP + j;
                        g_pval[o] = bv;
                        g_pidx[o] = ui * HS + bu;
                    }
                }
                __syncthreads();
            }

            // ring update: P0 <- P1 + E_s ; P1 <- E_s
            #pragma unroll
            for (int mi = 0; mi < 2; ++mi)
                #pragma unroll
                for (int ni = 0; ni < 4; ++ni)
                    #pragma unroll
                    for (int q = 0; q < 4; ++q) {
                        float e = acc[mi][ni][q];
                        P0[mi][ni][q] = P1[mi][ni][q] + e;
                        P1[mi][ni][q] = e;
                    }
            ++c_sl;
        }
    }
}

// ---------------------------------------------------------------------------
// Final argmax over the 126 valid diagonals per anchor (d = ui - i).
// Block per (pos, n), thread = ui.
// ---------------------------------------------------------------------------
__global__ __launch_bounds__(128) void reduce_argmax_kernel() {
    const int pos = blockIdx.x;
    const int n   = blockIdx.y;
    const int i   = pos / WP;
    const int t   = threadIdx.x;

    float v = -3.0e38f;
    int   u = 0x7fffffff;
    if (t < HS) {
        int dIdx = t - i + 61;   // always in [0, 186]
        size_t o = ((size_t)n * NDIAG + dIdx) * MVALID + pos;
        v = g_pval[o];
        u = g_pidx[o];
    }
    #pragma unroll
    for (int off = 16; off; off >>= 1) {
        float ov = __shfl_xor_sync(0xffffffffu, v, off);
        int   ou = __shfl_xor_sync(0xffffffffu, u, off);
        if (ov > v || (ov == v && ou < u)) { v = ov; u = ou; }
    }
    __shared__ float wsv[4];
    __shared__ int   wsi[4];
    if ((t & 31) == 0) { wsv[t >> 5] = v; wsi[t >> 5] = u; }
    __syncthreads();
    if (t == 0) {
        #pragma unroll
        for (int w = 1; w < 4; ++w)
            if (wsv[w] > wsv[0] || (wsv[w] == wsv[0] && wsi[w] < wsi[0])) {
                wsv[0] = wsv[w]; wsi[0] = wsi[w];
            }
        g_idx[n * MVALID + pos] = wsi[0];
    }
}

// ---------------------------------------------------------------------------
// L1 + clip + sum: block per (n, position), 128 threads = channels.
// ---------------------------------------------------------------------------
__global__ __launch_bounds__(128) void l1_kernel(const float* __restrict__ outf,
                                                 const float* __restrict__ colf,
                                                 float* __restrict__ d_out) {
    const int pos = blockIdx.x;
    const int n   = blockIdx.y;
    const int c   = threadIdx.x;

    const int i = pos / WP, j = pos % WP;
    const int u = g_idx[n * MVALID + pos];
    const int ui = u / HS, uj = u % HS;

    const float* po = outf + (((size_t)n * CCH + c) * H1 + i) * W1 + j;
    const float* pc = colf + (((size_t)n * CCH + c) * H2 + ui) * W2 + uj;

    float s = 0.0f;
    #pragma unroll
    for (int a = 0; a < 3; ++a)
        #pragma unroll
        for (int b = 0; b < 3; ++b)
            s += fabsf(po[a * W1 + b] - pc[a * W2 + b]);

    #pragma unroll
    for (int off = 16; off; off >>= 1) s += __shfl_xor_sync(0xffffffffu, s, off);

    __shared__ float ws[4];
    if ((threadIdx.x & 31) == 0) ws[threadIdx.x >> 5] = s;
    __syncthreads();
    if (threadIdx.x == 0) {
        float t = ws[0] + ws[1] + ws[2] + ws[3];
        atomicAdd(d_out, fminf(t, 1000.0f));
    }
}

__global__ void zero_out_kernel(float* p) { if (threadIdx.x == 0) p[0] = 0.0f; }

// ---------------------------------------------------------------------------
extern "C" void kernel_launch(void* const* d_in, const int* in_sizes, int n_in,
                              void* d_out, int out_size) {
    const float* outf = (const float*)d_in[0];
    const float* reff = (const float*)d_in[1];
    const float* shpf = (const float*)d_in[2];
    const float* colf = (const float*)d_in[3];
    float* out = (float*)d_out;

    cudaFuncSetAttribute(simdiag_kernel,
                         cudaFuncAttributeMaxDynamicSharedMemorySize, SMEM_BYTES);

    zero_out_kernel<<<1, 32>>>(out);

    {
        size_t tx = (size_t)NBATCH * 64 * 64 * KE;
        pack_xe<<<(int)((tx + 255) / 256), 256>>>(reff);
        size_t ty = (size_t)NBATCH * 128 * 128 * KE;
        pack_ye<<<(int)((ty + 255) / 256), 256>>>(shpf);
    }

    // diagonal-chain GEMM: grid (187 diagonals, 4 anchor chunks, 2 batches)
    simdiag_kernel<<<dim3(NDIAG, 4, NBATCH), 256, SMEM_BYTES>>>();

    reduce_argmax_kernel<<<dim3(MVALID, NBATCH), 128>>>();

    l1_kernel<<<dim3(MVALID, NBATCH), 128>>>(outf, colf, out);
}

// round 17
// speedup vs baseline: 4.8314x; 1.1477x over previous
#include <cuda_runtime.h>
#include <cuda_bf16.h>
#include <cstdint>

// ---------------------------------------------------------------------------
// PatchLoss via diagonal-sliced correlation:
//   E[(s,vs)][j,uj] = sum_{b,c} ref[c,s,j+b] * shape[c,vs,uj+b]   (K=384 GEMM)
//   sim[(i,j),(ui,uj)] = sum_a E[(i+a, ui+a)][j,uj]               (frag adds)
// argmax over (ui,uj) per anchor, then L1(out, color[argmax]) clip 1000, sum.
// R16: 128-thread CTAs (64j x 64uj, uj split in halves), 3 CTAs/SM.
// ---------------------------------------------------------------------------

#define NBATCH 2
#define CCH    128
#define H1     64
#define W1     64
#define H2     128
#define W2     128
#define WP     62
#define MVALID 3844
#define HS     126
#define KE     384            // 3 * 128
#define NDIAG  187            // d = ui - i in [-61, 125]
#define TI     16             // anchors per CTA chunk
#define KCH    64             // k per pipeline chunk
#define NKCH   6              // 384/64  (6 % NSTAGE == 0 -> static stages)
#define KP     72             // padded smem row stride (144 B)
#define NSTAGE 3

#define STAGE_ELEMS (128 * KP)                  // 64 Xe rows + 64 Ye rows
#define SMEM_BYTES  (NSTAGE * STAGE_ELEMS * 2)  // 55296

__device__ __nv_bfloat16 g_Xe[(size_t)NBATCH * 64 * 64 * KE];     // 6.3 MB
__device__ __nv_bfloat16 g_Ye[(size_t)NBATCH * 128 * 128 * KE];   // 25 MB
__device__ float g_pval[(size_t)NBATCH * NDIAG * 2 * MVALID];
__device__ int   g_pidx[(size_t)NBATCH * NDIAG * 2 * MVALID];
__device__ int   g_idx[NBATCH * MVALID];

// ---------------------------------------------------------------------------
// Pack Xe[n][s][j][b*128+c] = bf16(ref[n,c,s,j+b]), zero for j+b > 63.
// ---------------------------------------------------------------------------
__global__ void pack_xe(const float* __restrict__ ref) {
    size_t t = (size_t)blockIdx.x * blockDim.x + threadIdx.x;
    if (t >= (size_t)NBATCH * 64 * 64 * KE) return;
    int c = (int)(t % CCH);
    int b = (int)((t / CCH) % 3);
    int j = (int)((t / KE) % 64);
    int s = (int)((t / ((size_t)KE * 64)) % 64);
    int n = (int)(t / ((size_t)KE * 64 * 64));
    float v = (j + b < W1)
        ? ref[(((size_t)n * CCH + c) * H1 + s) * W1 + j + b] : 0.0f;
    g_Xe[t] = __float2bfloat16(v);
}

// Ye[n][vs][uj][b*128+c] = bf16(shape[n,c,vs,uj+b]), zero for uj+b > 127.
__global__ void pack_ye(const float* __restrict__ shp) {
    size_t t = (size_t)blockIdx.x * blockDim.x + threadIdx.x;
    if (t >= (size_t)NBATCH * 128 * 128 * KE) return;
    int c  = (int)(t % CCH);
    int b  = (int)((t / CCH) % 3);
    int uj = (int)((t / KE) % 128);
    int vs = (int)((t / ((size_t)KE * 128)) % 128);
    int n  = (int)(t / ((size_t)KE * 128 * 128));
    float v = (uj + b < W2)
        ? shp[(((size_t)n * CCH + c) * H2 + vs) * W2 + uj + b] : 0.0f;
    g_Ye[t] = __float2bfloat16(v);
}

// ---------------------------------------------------------------------------
__device__ __forceinline__ void cp_async16(uint32_t smem_dst, const void* gmem_src) {
    asm volatile("cp.async.cg.shared.global [%0], [%1], 16;\n"
                 :: "r"(smem_dst), "l"(gmem_src));
}

// ---------------------------------------------------------------------------
// Diagonal-chain GEMM + stencil + argmax.
// Grid (NDIAG, 4 anchor chunks * 2 uj-halves, NBATCH). 128 threads = 4 warps
// (2 wm x 2 wn), warp tile 32j x 32uj. Register rings P0/P1 hold a-sums.
// ---------------------------------------------------------------------------
__global__ __launch_bounds__(128, 3) void simdiag_kernel() {
    extern __shared__ __nv_bfloat16 dyn[];
    __shared__ float sv[2 * 64];
    __shared__ int   si[2 * 64];

    const int dIdx = blockIdx.x;
    const int d    = dIdx - 61;
    const int ch4  = blockIdx.y >> 1;    // anchor chunk 0..3
    const int h    = blockIdx.y & 1;     // uj half
    const int n    = blockIdx.z;

    int i_lo = ch4 * TI;
    if (-d > i_lo) i_lo = -d;
    int i_hi = ch4 * TI + TI - 1;
    if (i_hi > 61) i_hi = 61;
    if (i_hi > 125 - d) i_hi = 125 - d;
    if (i_lo > i_hi) return;

    const int nsl = i_hi + 3 - i_lo;     // slices s = i_lo .. i_hi+2 (>= 3)

    const __nv_bfloat16* Xb = g_Xe + ((size_t)n * 64 + i_lo) * 64 * KE;
    const __nv_bfloat16* Yb = g_Ye +
        (((size_t)n * 128 + (i_lo + d)) * 128 + h * 64) * KE;

    const int tid  = threadIdx.x;
    const int lane = tid & 31;
    const int wid  = tid >> 5;
    const int wm   = wid >> 1;   // 0..1 -> j rows wm*32
    const int wn   = wid & 1;    // 0..1 -> uj cols wn*32
    const int lrow = lane & 15;
    const int lcol = (lane >> 4) << 3;

    // per-thread cp.async coords: 4 chunks X + 4 chunks Y
    // ch = tid + q*128 in [0,512): row = ch>>3 (0..63), k16 = ch&7

    auto issue = [&](int isl, int ikc, int stg) {
        const int k0 = ikc * KCH;
        uint32_t st = (uint32_t)__cvta_generic_to_shared(dyn + stg * STAGE_ELEMS);
        const __nv_bfloat16* xs = Xb + (size_t)isl * 64 * KE + k0;
        const __nv_bfloat16* ys = Yb + (size_t)isl * 128 * KE + k0;
        #pragma unroll
        for (int q = 0; q < 4; ++q) {
            int ch = tid + q * 128;
            int row = ch >> 3, k16 = ch & 7;
            cp_async16(st + (row * KP + k16 * 8) * 2,
                       xs + (size_t)row * KE + k16 * 8);
        }
        #pragma unroll
        for (int q = 0; q < 4; ++q) {
            int ch = tid + q * 128;
            int row = ch >> 3, k16 = ch & 7;
            cp_async16(st + ((64 + row) * KP + k16 * 8) * 2,
                       ys + (size_t)row * KE + k16 * 8);
        }
    };

    issue(0, 0, 0);
    asm volatile("cp.async.commit_group;\n" ::: "memory");
    issue(0, 1, 1);
    asm volatile("cp.async.commit_group;\n" ::: "memory");

    float acc[2][4][4], P0[2][4][4], P1[2][4][4];
    #pragma unroll
    for (int mi = 0; mi < 2; ++mi)
        #pragma unroll
        for (int ni = 0; ni < 4; ++ni)
            #pragma unroll
            for (int q = 0; q < 4; ++q) { P0[mi][ni][q] = 0.0f; P1[mi][ni][q] = 0.0f; }

    for (int sl = 0; sl < nsl; ++sl) {
        #pragma unroll
        for (int mi = 0; mi < 2; ++mi)
            #pragma unroll
            for (int ni = 0; ni < 4; ++ni)
                #pragma unroll
                for (int q = 0; q < 4; ++q) acc[mi][ni][q] = 0.0f;

        #pragma unroll
        for (int kc = 0; kc < NKCH; ++kc) {
            asm volatile("cp.async.wait_group 1;\n" ::: "memory");
            __syncthreads();

            // issue chunk (sl*6 + kc + 2); stage (kc+2)%3 — compile-time
            {
                const int isl = sl + ((kc + 2) >= NKCH ? 1 : 0);
                const int ikc = (kc + 2) % NKCH;
                if (isl < nsl) issue(isl, ikc, (kc + 2) % NSTAGE);
            }
            asm volatile("cp.async.commit_group;\n" ::: "memory");

            const __nv_bfloat16* sA = dyn + (kc % NSTAGE) * STAGE_ELEMS;

            #pragma unroll
            for (int kk = 0; kk < 4; ++kk) {
                uint32_t af[2][4], bf[4][2];
                #pragma unroll
                for (int mi = 0; mi < 2; ++mi) {
                    uint32_t addr = (uint32_t)__cvta_generic_to_shared(
                        sA + (wm * 32 + mi * 16 + lrow) * KP + kk * 16 + lcol);
                    asm volatile("ldmatrix.sync.aligned.m8n8.x4.shared.b16 {%0,%1,%2,%3}, [%4];"
                        : "=r"(af[mi][0]), "=r"(af[mi][1]), "=r"(af[mi][2]), "=r"(af[mi][3])
                        : "r"(addr));
                }
                #pragma unroll
                for (int nh = 0; nh < 2; ++nh) {
                    uint32_t r0, r1, r2, r3;
                    uint32_t addr = (uint32_t)__cvta_generic_to_shared(
                        sA + (64 + wn * 32 + nh * 16 + lrow) * KP + kk * 16 + lcol);
                    asm volatile("ldmatrix.sync.aligned.m8n8.x4.shared.b16 {%0,%1,%2,%3}, [%4];"
                        : "=r"(r0), "=r"(r1), "=r"(r2), "=r"(r3) : "r"(addr));
                    bf[nh * 2 + 0][0] = r0; bf[nh * 2 + 0][1] = r2;
                    bf[nh * 2 + 1][0] = r1; bf[nh * 2 + 1][1] = r3;
                }
                #pragma unroll
                for (int mi = 0; mi < 2; ++mi)
                    #pragma unroll
                    for (int ni = 0; ni < 4; ++ni)
                        asm volatile(
                            "mma.sync.aligned.m16n8k16.row.col.f32.bf16.bf16.f32 "
                            "{%0,%1,%2,%3}, {%4,%5,%6,%7}, {%8,%9}, {%0,%1,%2,%3};"
                            : "+f"(acc[mi][ni][0]), "+f"(acc[mi][ni][1]),
                              "+f"(acc[mi][ni][2]), "+f"(acc[mi][ni][3])
                            : "r"(af[mi][0]), "r"(af[mi][1]), "r"(af[mi][2]), "r"(af[mi][3]),
                              "r"(bf[ni][0]), "r"(bf[ni][1]));
            }
        }

        // ---- slice complete: emit anchor sl-2, then ring update ------------
        if (sl >= 2) {
            const int ianc = i_lo + sl - 2;
            const int ui   = ianc + d;
            #pragma unroll
            for (int mi = 0; mi < 2; ++mi)
                #pragma unroll
                for (int rh = 0; rh < 2; ++rh) {
                    float bv = -3.0e38f; int bu = 0;
                    #pragma unroll
                    for (int ni = 0; ni < 4; ++ni)
                        #pragma unroll
                        for (int chh = 0; chh < 2; ++chh) {
                            int uj = h * 64 + wn * 32 + ni * 8 + (lane & 3) * 2 + chh;
                            float v = P0[mi][ni][rh * 2 + chh] + acc[mi][ni][rh * 2 + chh];
                            if (uj < HS && v > bv) { bv = v; bu = uj; }
                        }
                    #pragma unroll
                    for (int off = 1; off <= 2; off <<= 1) {
                        float ov = __shfl_xor_sync(0xffffffffu, bv, off);
                        int   ou = __shfl_xor_sync(0xffffffffu, bu, off);
                        if (ov > bv || (ov == bv && ou < bu)) { bv = ov; bu = ou; }
                    }
                    if ((lane & 3) == 0) {
                        int row = wm * 32 + mi * 16 + rh * 8 + (lane >> 2);
                        sv[wn * 64 + row] = bv;
                        si[wn * 64 + row] = bu;
                    }
                }
            __syncthreads();
            if (tid < WP) {
                float bv = sv[tid]; int bu = si[tid];
                float ov = sv[64 + tid]; int ou = si[64 + tid];
                if (ov > bv || (ov == bv && ou < bu)) { bv = ov; bu = ou; }
                size_t o = (((size_t)n * NDIAG + dIdx) * 2 + h) * MVALID
                         + ianc * WP + tid;
                g_pval[o] = bv;
                g_pidx[o] = ui * HS + bu;
            }
            __syncthreads();
        }

        #pragma unroll
        for (int mi = 0; mi < 2; ++mi)
            #pragma unroll
            for (int ni = 0; ni < 4; ++ni)
                #pragma unroll
                for (int q = 0; q < 4; ++q) {
                    float e = acc[mi][ni][q];
                    P0[mi][ni][q] = P1[mi][ni][q] + e;
                    P1[mi][ni][q] = e;
                }
    }
}

// ---------------------------------------------------------------------------
// Final argmax over 126 diagonals x 2 halves per anchor.
// Block per (pos, n), 256 threads: t = half*128 + ui.
// ---------------------------------------------------------------------------
__global__ __launch_bounds__(256) void reduce_argmax_kernel() {
    const int pos = blockIdx.x;
    const int n   = blockIdx.y;
    const int i   = pos / WP;
    const int t   = threadIdx.x;
    const int half = t >> 7;
    const int ui   = t & 127;

    float v = -3.0e38f;
    int   u = 0x7fffffff;
    if (ui < HS) {
        int dIdx = ui - i + 61;   // in [0, 186]
        size_t o = (((size_t)n * NDIAG + dIdx) * 2 + half) * MVALID + pos;
        v = g_pval[o];
        u = g_pidx[o];
    }
    #pragma unroll
    for (int off = 16; off; off >>= 1) {
        float ov = __shfl_xor_sync(0xffffffffu, v, off);
        int   ou = __shfl_xor_sync(0xffffffffu, u, off);
        if (ov > v || (ov == v && ou < u)) { v = ov; u = ou; }
    }
    __shared__ float wsv[8];
    __shared__ int   wsi[8];
    if ((t & 31) == 0) { wsv[t >> 5] = v; wsi[t >> 5] = u; }
    __syncthreads();
    if (t == 0) {
        #pragma unroll
        for (int w = 1; w < 8; ++w)
            if (wsv[w] > wsv[0] || (wsv[w] == wsv[0] && wsi[w] < wsi[0])) {
                wsv[0] = wsv[w]; wsi[0] = wsi[w];
            }
        g_idx[n * MVALID + pos] = wsi[0];
    }
}

// ---------------------------------------------------------------------------
// L1 + clip + sum: block per (n, position), 128 threads = channels.
// ---------------------------------------------------------------------------
__global__ __launch_bounds__(128) void l1_kernel(const float* __restrict__ outf,
                                                 const float* __restrict__ colf,
                                                 float* __restrict__ d_out) {
    const int pos = blockIdx.x;
    const int n   = blockIdx.y;
    const int c   = threadIdx.x;

    const int i = pos / WP, j = pos % WP;
    const int u = g_idx[n * MVALID + pos];
    const int ui = u / HS, uj = u % HS;

    const float* po = outf + (((size_t)n * CCH + c) * H1 + i) * W1 + j;
    const float* pc = colf + (((size_t)n * CCH + c) * H2 + ui) * W2 + uj;

    float s = 0.0f;
    #pragma unroll
    for (int a = 0; a < 3; ++a)
        #pragma unroll
        for (int b = 0; b < 3; ++b)
            s += fabsf(po[a * W1 + b] - pc[a * W2 + b]);

    #pragma unroll
    for (int off = 16; off; off >>= 1) s += __shfl_xor_sync(0xffffffffu, s, off);

    __shared__ float ws[4];
    if ((threadIdx.x & 31) == 0) ws[threadIdx.x >> 5] = s;
    __syncthreads();
    if (threadIdx.x == 0) {
        float t = ws[0] + ws[1] + ws[2] + ws[3];
        atomicAdd(d_out, fminf(t, 1000.0f));
    }
}

__global__ void zero_out_kernel(float* p) { if (threadIdx.x == 0) p[0] = 0.0f; }

// ---------------------------------------------------------------------------
extern "C" void kernel_launch(void* const* d_in, const int* in_sizes, int n_in,
                              void* d_out, int out_size) {
    const float* outf = (const float*)d_in[0];
    const float* reff = (const float*)d_in[1];
    const float* shpf = (const float*)d_in[2];
    const float* colf = (const float*)d_in[3];
    float* out = (float*)d_out;

    cudaFuncSetAttribute(simdiag_kernel,
                         cudaFuncAttributeMaxDynamicSharedMemorySize, SMEM_BYTES);

    zero_out_kernel<<<1, 32>>>(out);

    {
        size_t tx = (size_t)NBATCH * 64 * 64 * KE;
        pack_xe<<<(int)((tx + 255) / 256), 256>>>(reff);
        size_t ty = (size_t)NBATCH * 128 * 128 * KE;
        pack_ye<<<(int)((ty + 255) / 256), 256>>>(shpf);
    }

    // grid: (187 diagonals, 4 anchor chunks x 2 uj halves, 2 batches)
    simdiag_kernel<<<dim3(NDIAG, 8, NBATCH), 128, SMEM_BYTES>>>();

    reduce_argmax_kernel<<<dim3(MVALID, NBATCH), 256>>>();

    l1_kernel<<<dim3(MVALID, NBATCH), 128>>>(outf, colf, out);
}